// round 11
// baseline (speedup 1.0000x reference)
#include <cuda_runtime.h>

// IF spiking neuron forward (R11 = R10 .cg + software-pipelined loads):
//   x: [T=8, N=4194304] fp32, thresh: [1] fp32
//   mem = 0.5*thr; per t: m = mem + x[t]; s = (m>=thr); out[t] = s*thr; mem = m - s*thr
//
// Evidence (device time / DRAM% / occ):
//   R10 .cg full front-batch (40r):  35.8us / 75.5% / 62%   <- best
//   R6  plain (32r):                 36.2us / 74.7% / 82%
//   R8  TPB128 plain:                36.4us / 74.4%
//   R4  .cs TPB512:                  37.1us / 72.9%
//   R5  .cs + 32-reg cap:            43.1us (cap serialized the load batch)
// R11: keep .cg (L1 bypass won), but pipeline loads at depth 6 so the live
// buffer shrinks below the full 32-reg batch -> fits a 36-reg budget
// (__launch_bounds__(256,7): 7 CTAs/SM, 1792 thr) = high MLP AND high occ.

#define T_STEPS 8
#define N_NEURONS (256 / T_STEPS * 512 * 16 * 16)   // 4,194,304
#define N4 (N_NEURONS / 4)                           // 1,048,576 float4 per timestep
#define TPB 256
#define DEPTH 6                                      // loads in flight

__global__ __launch_bounds__(TPB, 7) void if_forward_kernel(
    const float4* __restrict__ x,
    const float* __restrict__ thresh,
    float4* __restrict__ out)
{
    const int i = blockIdx.x * TPB + threadIdx.x;  // grid exactly covers N4
    const float thr = __ldg(thresh);

    // Software pipeline: prime DEPTH loads, then consume t / issue t+DEPTH.
    float4 xv[T_STEPS];
#pragma unroll
    for (int t = 0; t < DEPTH; t++) {
        xv[t] = __ldcg(&x[(size_t)t * N4 + i]);
    }

    float m0 = 0.5f * thr, m1 = m0, m2 = m0, m3 = m0;

#pragma unroll
    for (int t = 0; t < T_STEPS; t++) {
        if (t + DEPTH < T_STEPS) {
            xv[t + DEPTH] = __ldcg(&x[(size_t)(t + DEPTH) * N4 + i]);
        }
        m0 += xv[t].x;
        m1 += xv[t].y;
        m2 += xv[t].z;
        m3 += xv[t].w;
        float4 sp;
        sp.x = (m0 >= thr) ? thr : 0.0f;
        sp.y = (m1 >= thr) ? thr : 0.0f;
        sp.z = (m2 >= thr) ? thr : 0.0f;
        sp.w = (m3 >= thr) ? thr : 0.0f;
        m0 -= sp.x;
        m1 -= sp.y;
        m2 -= sp.z;
        m3 -= sp.w;
        out[(size_t)t * N4 + i] = sp;
    }
}

extern "C" void kernel_launch(void* const* d_in, const int* in_sizes, int n_in,
                              void* d_out, int out_size) {
    const float4* x = (const float4*)d_in[0];
    const float* thresh = (const float*)d_in[1];
    float4* out = (float4*)d_out;

    const int blocks = N4 / TPB;  // 4096, exact
    if_forward_kernel<<<blocks, TPB>>>(x, thresh, out);
}

// round 12
// speedup vs baseline: 1.0289x; 1.0289x over previous
#include <cuda_runtime.h>

// IF spiking neuron forward (R12 = R10 verbatim — confirmation run of best):
//   x: [T=8, N=4194304] fp32, thresh: [1] fp32
//   mem = 0.5*thr; per t: m = mem + x[t]; s = (m>=thr); out[t] = s*thr; mem = m - s*thr
//
// Final evidence table (device time / DRAM% / occ / regs):
//   R10 .cg, free regs, batch-8:  35.8us / 75.5% / 62% / 40   <- best
//   R6  plain, free regs:         36.2us / 74.7% / 82% / 32
//   R8  TPB128 plain:             36.4us / 74.4%
//   R4  .cs TPB512:               37.1us / 72.9%
//   R3  ITEMS=2 (occ 31%):        38.3us / 70.6%
//   R7  persistent 1184 CTAs:     39.0us / 69.9%
//   R11 pipelined + reg cap:      41.5us / 69.5%  (cap collapsed load MLP)
//   R5  .cs + reg cap:            43.1us / 69.8%
// Laws learned: (1) never cap registers — ptxas reuses the load buffer and
// serializes the 8-deep MLP, which dominates occupancy; (2) .cg (L1 bypass,
// default L2 policy) wins — L1 fill is pure overhead for single-touch data,
// while .cs evict-first L2 policy harms. ~75% of 8TB/s = 1:1 R/W turnaround
// ceiling; traffic is irreducible (128MiB in + 128MiB out, single touch).

#define T_STEPS 8
#define N_NEURONS (256 / T_STEPS * 512 * 16 * 16)   // 4,194,304
#define N4 (N_NEURONS / 4)                           // 1,048,576 float4 per timestep
#define TPB 256

__global__ __launch_bounds__(TPB) void if_forward_kernel(
    const float4* __restrict__ x,
    const float* __restrict__ thresh,
    float4* __restrict__ out)
{
    const int i = blockIdx.x * TPB + threadIdx.x;  // grid exactly covers N4
    const float thr = __ldg(thresh);

    // Front-batch all 8 timestep loads; .cg = cache at L2 only (skip L1 fill,
    // keep default L2 replacement policy). ptxas keeps all 8 float4 live
    // (40 regs) -> full 8-deep MLP per thread.
    float4 xv[T_STEPS];
#pragma unroll
    for (int t = 0; t < T_STEPS; t++) {
        xv[t] = __ldcg(&x[(size_t)t * N4 + i]);
    }

    float m0 = 0.5f * thr, m1 = m0, m2 = m0, m3 = m0;

#pragma unroll
    for (int t = 0; t < T_STEPS; t++) {
        m0 += xv[t].x;
        m1 += xv[t].y;
        m2 += xv[t].z;
        m3 += xv[t].w;
        float4 sp;
        sp.x = (m0 >= thr) ? thr : 0.0f;
        sp.y = (m1 >= thr) ? thr : 0.0f;
        sp.z = (m2 >= thr) ? thr : 0.0f;
        sp.w = (m3 >= thr) ? thr : 0.0f;
        m0 -= sp.x;
        m1 -= sp.y;
        m2 -= sp.z;
        m3 -= sp.w;
        out[(size_t)t * N4 + i] = sp;
    }
}

extern "C" void kernel_launch(void* const* d_in, const int* in_sizes, int n_in,
                              void* d_out, int out_size) {
    const float4* x = (const float4*)d_in[0];
    const float* thresh = (const float*)d_in[1];
    float4* out = (float4*)d_out;

    const int blocks = N4 / TPB;  // 4096, exact
    if_forward_kernel<<<blocks, TPB>>>(x, thresh, out);
}

// round 13
// speedup vs baseline: 1.0348x; 1.0057x over previous
#include <cuda_runtime.h>

// IF spiking neuron forward — FINAL (R13 = measured-best config, R10/R12):
//   x: [T=8, N=4194304] fp32, thresh: [1] fp32
//   mem = 0.5*thr; per t: m = mem + x[t]; s = (m>=thr); out[t] = s*thr; mem = m - s*thr
//
// Converged at the 1:1 read/write-stream roofline: 5.9-6.0 TB/s (74-75% of
// 8 TB/s spec), ~36.0us device time. Full evidence table (device / DRAM%):
//   R10/R12 .cg, free regs, batch-8:  35.8-36.2us / 74.5-75.5%   <- FINAL
//   R6  plain, free regs:             36.2us / 74.7%
//   R8  TPB128 plain:                 36.4us / 74.4%
//   R4  .cs TPB512:                   37.1us / 72.9%
//   R3  ITEMS=2 (occ 31%):            38.3us / 70.6%
//   R7  persistent 1184 CTAs:         39.0us / 69.9%
//   R11 pipelined + reg cap:          41.5us / 69.5%
//   R5  .cs + reg cap:                43.1us / 69.8%
// Design laws (A/B-proven on this problem):
//   1. Front-batch all 8 timestep LDG.128s per thread; NEVER cap registers —
//      any cap makes ptxas reuse the load buffer and serialize the MLP,
//      which costs far more than the occupancy it buys (62% occ w/ MLP8
//      beats 86% occ w/ serialized loads by 5.7us).
//   2. __ldcg (L1 bypass, default L2 policy): L1 fill is pure overhead for
//      single-touch data; .cs evict-first L2 policy actively harms.
//   3. Multi-wave 4096-CTA launch beats a persistent one-wave grid (fresh
//      CTAs keep load bursts flowing; persistent CTAs phase-lock into
//      burst-drain cycles).
// Traffic is irreducible (128MiB in + 128MiB out, single touch); compute
// pipes are <12% busy. This is the roofline.

#define T_STEPS 8
#define N_NEURONS (256 / T_STEPS * 512 * 16 * 16)   // 4,194,304
#define N4 (N_NEURONS / 4)                           // 1,048,576 float4 per timestep
#define TPB 256

__global__ __launch_bounds__(TPB) void if_forward_kernel(
    const float4* __restrict__ x,
    const float* __restrict__ thresh,
    float4* __restrict__ out)
{
    const int i = blockIdx.x * TPB + threadIdx.x;  // grid exactly covers N4
    const float thr = __ldg(thresh);

    // Front-batch all 8 timestep loads; .cg = cache at L2 only.
    float4 xv[T_STEPS];
#pragma unroll
    for (int t = 0; t < T_STEPS; t++) {
        xv[t] = __ldcg(&x[(size_t)t * N4 + i]);
    }

    float m0 = 0.5f * thr, m1 = m0, m2 = m0, m3 = m0;

#pragma unroll
    for (int t = 0; t < T_STEPS; t++) {
        m0 += xv[t].x;
        m1 += xv[t].y;
        m2 += xv[t].z;
        m3 += xv[t].w;
        float4 sp;
        sp.x = (m0 >= thr) ? thr : 0.0f;
        sp.y = (m1 >= thr) ? thr : 0.0f;
        sp.z = (m2 >= thr) ? thr : 0.0f;
        sp.w = (m3 >= thr) ? thr : 0.0f;
        m0 -= sp.x;
        m1 -= sp.y;
        m2 -= sp.z;
        m3 -= sp.w;
        out[(size_t)t * N4 + i] = sp;
    }
}

extern "C" void kernel_launch(void* const* d_in, const int* in_sizes, int n_in,
                              void* d_out, int out_size) {
    const float4* x = (const float4*)d_in[0];
    const float* thresh = (const float*)d_in[1];
    float4* out = (float4*)d_out;

    const int blocks = N4 / TPB;  // 4096, exact
    if_forward_kernel<<<blocks, TPB>>>(x, thresh, out);
}

// round 14
// speedup vs baseline: 1.0392x; 1.0043x over previous
#include <cuda_runtime.h>

// IF spiking neuron forward (R14 = .cg loads + TPB=128 — last untested cell):
//   x: [T=8, N=4194304] fp32, thresh: [1] fp32
//   mem = 0.5*thr; per t: m = mem + x[t]; s = (m>=thr); out[t] = s*thr; mem = m - s*thr
//
// Evidence (device time / DRAM% / occ / regs):
//   R10/12/13 .cg TPB256 batch-8:  35.8-36.4us / 74.2-75.5% / 63% / 40  <- best
//   R6  plain TPB256:              36.2us / 74.7% / 82% / 32
//   R8  plain TPB128:              36.4us / 74.4%
//   R4  .cs TPB512:                37.1us / 72.9%
//   R3  ITEMS=2:                   38.3us / 70.6%
//   R7  persistent 1184:           39.0us / 69.9%
//   R11 pipeline+cap:              41.5us / 69.5%
//   R5  .cs+cap:                   43.1us / 69.8%
// R14 tests .cg x TPB128: at 40 regs both TPB choices resident 1536 thr/SM,
// but TPB128 doubles independent CTA streams (12/SM) -> finer load-burst
// quanta at L1tex, finer retirement. Same regs/occ; zero downside expected.
// Laws: never cap regs (kills 8-deep load MLP); .cg wins (no L1 fill for
// single-touch data, default L2 policy preserved); multi-wave beats persistent.

#define T_STEPS 8
#define N_NEURONS (256 / T_STEPS * 512 * 16 * 16)   // 4,194,304
#define N4 (N_NEURONS / 4)                           // 1,048,576 float4 per timestep
#define TPB 128

__global__ __launch_bounds__(TPB) void if_forward_kernel(
    const float4* __restrict__ x,
    const float* __restrict__ thresh,
    float4* __restrict__ out)
{
    const int i = blockIdx.x * TPB + threadIdx.x;  // grid exactly covers N4
    const float thr = __ldg(thresh);

    // Front-batch all 8 timestep loads; .cg = cache at L2 only.
    float4 xv[T_STEPS];
#pragma unroll
    for (int t = 0; t < T_STEPS; t++) {
        xv[t] = __ldcg(&x[(size_t)t * N4 + i]);
    }

    float m0 = 0.5f * thr, m1 = m0, m2 = m0, m3 = m0;

#pragma unroll
    for (int t = 0; t < T_STEPS; t++) {
        m0 += xv[t].x;
        m1 += xv[t].y;
        m2 += xv[t].z;
        m3 += xv[t].w;
        float4 sp;
        sp.x = (m0 >= thr) ? thr : 0.0f;
        sp.y = (m1 >= thr) ? thr : 0.0f;
        sp.z = (m2 >= thr) ? thr : 0.0f;
        sp.w = (m3 >= thr) ? thr : 0.0f;
        m0 -= sp.x;
        m1 -= sp.y;
        m2 -= sp.z;
        m3 -= sp.w;
        out[(size_t)t * N4 + i] = sp;
    }
}

extern "C" void kernel_launch(void* const* d_in, const int* in_sizes, int n_in,
                              void* d_out, int out_size) {
    const float4* x = (const float4*)d_in[0];
    const float* thresh = (const float*)d_in[1];
    float4* out = (float4*)d_out;

    const int blocks = N4 / TPB;  // 8192, exact
    if_forward_kernel<<<blocks, TPB>>>(x, thresh, out);
}

// round 15
// speedup vs baseline: 1.0720x; 1.0316x over previous
#include <cuda_runtime.h>

// IF spiking neuron forward (R15 = .cg + TPB=64 — extrapolating the winning
// CTA-fineness gradient one step):
//   x: [T=8, N=4194304] fp32, thresh: [1] fp32
//   mem = 0.5*thr; per t: m = mem + x[t]; s = (m>=thr); out[t] = s*thr; mem = m - s*thr
//
// Evidence (device time / DRAM% / occ / regs):
//   R14 .cg TPB128 batch-8:        35.5us / 76.0% / 62% / 40   <- best
//   R10/12/13 .cg TPB256:          35.8-36.4us / 74.2-75.5%
//   R6  plain TPB256:              36.2us / 74.7% / 82% / 32
//   R8  plain TPB128:              36.4us / 74.4%
//   R4  .cs TPB512:                37.1us / 72.9%
//   R7  persistent 1184:           39.0us / 69.9%
//   R11 pipeline+cap:              41.5us / 69.5%
//   R5  .cs+cap:                   43.1us / 69.8%
// DRAM% is monotone in CTA fineness at fixed MLP (TPB512 72.9 -> 256 74.5 ->
// 128 76.0): more independent CTA streams/SM = smoother load-burst interleave.
// R15 tests TPB=64 (24 CTAs/SM, same 1536 thr resident, same 40 regs).
// Decision: win -> final; neutral/regress -> R14 is final.
// Laws: never cap regs (kills the 8-deep load MLP); .cg wins (skip L1 fill
// for single-touch data, keep default L2 policy); multi-wave beats persistent.

#define T_STEPS 8
#define N_NEURONS (256 / T_STEPS * 512 * 16 * 16)   // 4,194,304
#define N4 (N_NEURONS / 4)                           // 1,048,576 float4 per timestep
#define TPB 64

__global__ __launch_bounds__(TPB) void if_forward_kernel(
    const float4* __restrict__ x,
    const float* __restrict__ thresh,
    float4* __restrict__ out)
{
    const int i = blockIdx.x * TPB + threadIdx.x;  // grid exactly covers N4
    const float thr = __ldg(thresh);

    // Front-batch all 8 timestep loads; .cg = cache at L2 only.
    float4 xv[T_STEPS];
#pragma unroll
    for (int t = 0; t < T_STEPS; t++) {
        xv[t] = __ldcg(&x[(size_t)t * N4 + i]);
    }

    float m0 = 0.5f * thr, m1 = m0, m2 = m0, m3 = m0;

#pragma unroll
    for (int t = 0; t < T_STEPS; t++) {
        m0 += xv[t].x;
        m1 += xv[t].y;
        m2 += xv[t].z;
        m3 += xv[t].w;
        float4 sp;
        sp.x = (m0 >= thr) ? thr : 0.0f;
        sp.y = (m1 >= thr) ? thr : 0.0f;
        sp.z = (m2 >= thr) ? thr : 0.0f;
        sp.w = (m3 >= thr) ? thr : 0.0f;
        m0 -= sp.x;
        m1 -= sp.y;
        m2 -= sp.z;
        m3 -= sp.w;
        out[(size_t)t * N4 + i] = sp;
    }
}

extern "C" void kernel_launch(void* const* d_in, const int* in_sizes, int n_in,
                              void* d_out, int out_size) {
    const float4* x = (const float4*)d_in[0];
    const float* thresh = (const float*)d_in[1];
    float4* out = (float4*)d_out;

    const int blocks = N4 / TPB;  // 16384, exact
    if_forward_kernel<<<blocks, TPB>>>(x, thresh, out);
}